// round 8
// baseline (speedup 1.0000x reference)
#include <cuda_runtime.h>
#include <cuda_bf16.h>
#include <cuda_fp16.h>

#define FEATS 64
#define MAX_NODES 100000
#define MAX_EDGES 1000000
#define SCAN_BLK 1024

// ---- scratch (__device__ globals; no allocs allowed) ----
__device__ float  g_sum[(size_t)MAX_NODES * FEATS];   // fp32 neighbor sums
__device__ float  g_deg[MAX_NODES];                   // degree (float)
__device__ __half g_xh[(size_t)MAX_NODES * FEATS];    // fp16 copy of x
__device__ int    g_count[MAX_NODES];
__device__ int    g_incl[MAX_NODES];
__device__ int    g_start[MAX_NODES];
__device__ int    g_cursor[MAX_NODES];
__device__ int    g_blocksums[128];
__device__ int    g_edge_src[MAX_EDGES];

// ---------------------------------------------------------------------------
// packed f32x2 FMA (sm_103a FFMA2)
// ---------------------------------------------------------------------------
__device__ __forceinline__ unsigned long long fma2(unsigned long long a,
                                                   unsigned long long b,
                                                   unsigned long long c) {
    unsigned long long d;
    asm("fma.rn.f32x2 %0, %1, %2, %3;" : "=l"(d) : "l"(a), "l"(b), "l"(c));
    return d;
}

// ---------------------------------------------------------------------------
// 1) zero int degree counters
// ---------------------------------------------------------------------------
__global__ void zero_counts(int n_nodes) {
    int i = blockIdx.x * blockDim.x + threadIdx.x;
    if (i < n_nodes) g_count[i] = 0;
}

// ---------------------------------------------------------------------------
// 2) histogram of dst (scalar — proven fastest)
// ---------------------------------------------------------------------------
__global__ void hist_kernel(const int* __restrict__ dst, int n_edges) {
    int e = blockIdx.x * blockDim.x + threadIdx.x;
    if (e < n_edges) atomicAdd(&g_count[dst[e]], 1);
}

// ---------------------------------------------------------------------------
// 3) x -> fp16 copy (float4 in, 8B packed out)
// ---------------------------------------------------------------------------
__global__ void tohalf_kernel(const float* __restrict__ x, int n4) {
    int i = blockIdx.x * blockDim.x + threadIdx.x;
    if (i < n4) {
        float4 v = __ldg(&reinterpret_cast<const float4*>(x)[i]);
        __half2 h0 = __floats2half2_rn(v.x, v.y);
        __half2 h1 = __floats2half2_rn(v.z, v.w);
        uint2 u;
        u.x = *reinterpret_cast<unsigned int*>(&h0);
        u.y = *reinterpret_cast<unsigned int*>(&h1);
        reinterpret_cast<uint2*>(g_xh)[i] = u;
    }
}

// ---------------------------------------------------------------------------
// 4a) coalesced per-block (1024) inclusive scan + block totals
// ---------------------------------------------------------------------------
__global__ __launch_bounds__(SCAN_BLK) void scan1(int n_nodes) {
    __shared__ int s[SCAN_BLK];
    int i = blockIdx.x * SCAN_BLK + threadIdx.x;
    int v = (i < n_nodes) ? g_count[i] : 0;
    s[threadIdx.x] = v;
    __syncthreads();
    #pragma unroll
    for (int off = 1; off < SCAN_BLK; off <<= 1) {
        int t = (threadIdx.x >= off) ? s[threadIdx.x - off] : 0;
        __syncthreads();
        s[threadIdx.x] += t;
        __syncthreads();
    }
    if (i < n_nodes) g_incl[i] = s[threadIdx.x];
    if (threadIdx.x == SCAN_BLK - 1) g_blocksums[blockIdx.x] = s[SCAN_BLK - 1];
}

// ---------------------------------------------------------------------------
// 4b) finalize: redundant scan of block sums + row starts + cursors + degree
// ---------------------------------------------------------------------------
__global__ __launch_bounds__(256) void scan3(int n_nodes, int nb) {
    __shared__ int sbs[128];
    int t = threadIdx.x;
    if (t < 128) sbs[t] = (t < nb) ? g_blocksums[t] : 0;
    __syncthreads();
    #pragma unroll
    for (int off = 1; off < 128; off <<= 1) {
        int v = 0;
        if (t < 128 && t >= off) v = sbs[t - off];
        __syncthreads();
        if (t < 128) sbs[t] += v;
        __syncthreads();
    }
    int i = blockIdx.x * 256 + t;
    if (i < n_nodes) {
        int chunk = i / SCAN_BLK;
        int pre = (chunk == 0) ? 0 : sbs[chunk - 1];
        int cnt = g_count[i];
        int st = g_incl[i] - cnt + pre;
        g_start[i]  = st;
        g_cursor[i] = st;
        g_deg[i]    = (float)cnt;
    }
}

// ---------------------------------------------------------------------------
// 5) reorder (scalar — proven fastest)
// ---------------------------------------------------------------------------
__global__ void reorder_kernel(const int* __restrict__ src,
                               const int* __restrict__ dst, int n_edges) {
    int e = blockIdx.x * blockDim.x + threadIdx.x;
    if (e < n_edges) {
        int p = atomicAdd(&g_cursor[dst[e]], 1);
        g_edge_src[p] = src[e];
    }
}

// ---------------------------------------------------------------------------
// 6) gather (fp16 rows): 16-lane group per node, 8B per lane (1 line per row),
//    fp32 accumulation, predicated batched remainder (no serial tail chain).
// ---------------------------------------------------------------------------
__global__ __launch_bounds__(256) void gather_kernel(int n_nodes) {
    int grp  = (blockIdx.x * blockDim.x + threadIdx.x) >> 4;
    int lane = threadIdx.x & 15;
    if (grp >= n_nodes) return;
    int s0  = g_start[grp];
    int deg = g_count[grp];
    const uint2* xh = reinterpret_cast<const uint2*>(g_xh);
    float4 acc = make_float4(0.f, 0.f, 0.f, 0.f);

    #define ACC_U2(u) do {                                            \
        __half2 h0 = *reinterpret_cast<__half2*>(&(u).x);             \
        __half2 h1 = *reinterpret_cast<__half2*>(&(u).y);             \
        float2 f0 = __half22float2(h0);                               \
        float2 f1 = __half22float2(h1);                               \
        acc.x += f0.x;  acc.y += f0.y;  acc.z += f1.x;  acc.w += f1.y;\
    } while (0)

    int j = 0;
    for (; j + 4 <= deg; j += 4) {
        int i0 = __ldg(&g_edge_src[s0 + j + 0]);
        int i1 = __ldg(&g_edge_src[s0 + j + 1]);
        int i2 = __ldg(&g_edge_src[s0 + j + 2]);
        int i3 = __ldg(&g_edge_src[s0 + j + 3]);
        uint2 u0 = __ldg(&xh[(size_t)i0 * 16 + lane]);
        uint2 u1 = __ldg(&xh[(size_t)i1 * 16 + lane]);
        uint2 u2 = __ldg(&xh[(size_t)i2 * 16 + lane]);
        uint2 u3 = __ldg(&xh[(size_t)i3 * 16 + lane]);
        ACC_U2(u0);  ACC_U2(u1);  ACC_U2(u2);  ACC_U2(u3);
    }
    int rem = deg - j;                      // 0..3
    if (rem > 0) {
        int i0 = __ldg(&g_edge_src[s0 + j]);
        int i1 = (rem > 1) ? __ldg(&g_edge_src[s0 + j + 1]) : 0;
        int i2 = (rem > 2) ? __ldg(&g_edge_src[s0 + j + 2]) : 0;
        uint2 z = make_uint2(0u, 0u);       // half bits 0 == +0.0
        uint2 u0 = __ldg(&xh[(size_t)i0 * 16 + lane]);
        uint2 u1 = (rem > 1) ? __ldg(&xh[(size_t)i1 * 16 + lane]) : z;
        uint2 u2 = (rem > 2) ? __ldg(&xh[(size_t)i2 * 16 + lane]) : z;
        ACC_U2(u0);  ACC_U2(u1);  ACC_U2(u2);
    }
    #undef ACC_U2

    reinterpret_cast<float4*>(g_sum)[(size_t)grp * 16 + lane] = acc;
}

// ---------------------------------------------------------------------------
// 7) out = relu(x@Ws + (sum/max(deg,1))@Wn + b)   — verbatim passing kernel
// ---------------------------------------------------------------------------
#define SA2_STRIDE 65
#define SMEM_A_BYTES (64 * SA2_STRIDE * 8)                 // 33280
#define SMEM_TOTAL (SMEM_A_BYTES + 2 * 16384 + 512)        // 66560

__global__ __launch_bounds__(256) void out_kernel(const float* __restrict__ x,
                                                  const float* __restrict__ Ws,
                                                  const float* __restrict__ Wn,
                                                  const float* __restrict__ b,
                                                  float* __restrict__ out,
                                                  int n_rows) {
    extern __shared__ char smem[];
    float2* sA2 = reinterpret_cast<float2*>(smem);
    float4* sWs = reinterpret_cast<float4*>(smem + SMEM_A_BYTES);
    float4* sWn = reinterpret_cast<float4*>(smem + SMEM_A_BYTES + 16384);
    float*  sb   = reinterpret_cast<float*>(smem + SMEM_A_BYTES + 32768);
    float*  sinv = sb + 64;

    int tid  = threadIdx.x;
    int row0 = blockIdx.x * 64;

    {
        const float4* gWs = reinterpret_cast<const float4*>(Ws);
        const float4* gWn = reinterpret_cast<const float4*>(Wn);
        #pragma unroll
        for (int i = 0; i < 4; i++) {
            int idx = tid + 256 * i;
            sWs[idx] = __ldg(&gWs[idx]);
            sWn[idx] = __ldg(&gWn[idx]);
        }
        if (tid < FEATS) sb[tid] = b[tid];
        if (tid < 64) {
            int r = row0 + tid;
            float dg = (r < n_rows) ? g_deg[r] : 1.0f;
            sinv[tid] = 1.0f / fmaxf(dg, 1.0f);
        }
    }

    {
        const float4* gx = reinterpret_cast<const float4*>(x);
        #pragma unroll
        for (int i = 0; i < 4; i++) {
            int idx = tid + 256 * i;
            int r = idx >> 4, c = idx & 15;
            int grow = row0 + r;
            float4 v = make_float4(0.f, 0.f, 0.f, 0.f);
            if (grow < n_rows) v = __ldg(&gx[(size_t)grow * 16 + c]);
            float2* dstp = &sA2[r * SA2_STRIDE + c * 4];
            dstp[0] = make_float2(v.x, v.x);
            dstp[1] = make_float2(v.y, v.y);
            dstp[2] = make_float2(v.z, v.z);
            dstp[3] = make_float2(v.w, v.w);
        }
    }
    __syncthreads();

    int ty = tid >> 4;
    int tx = tid & 15;

    unsigned long long acc[4][2];
    #pragma unroll
    for (int r = 0; r < 4; r++) { acc[r][0] = 0ull; acc[r][1] = 0ull; }

    const unsigned long long* a0p =
        reinterpret_cast<const unsigned long long*>(&sA2[(ty * 4 + 0) * SA2_STRIDE]);
    const unsigned long long* a1p = a0p + SA2_STRIDE;
    const unsigned long long* a2p = a1p + SA2_STRIDE;
    const unsigned long long* a3p = a2p + SA2_STRIDE;

    #pragma unroll 16
    for (int k = 0; k < FEATS; k++) {
        ulonglong2 w = *reinterpret_cast<const ulonglong2*>(&sWs[k * 16 + tx]);
        unsigned long long a0 = a0p[k], a1 = a1p[k], a2 = a2p[k], a3 = a3p[k];
        acc[0][0] = fma2(a0, w.x, acc[0][0]);  acc[0][1] = fma2(a0, w.y, acc[0][1]);
        acc[1][0] = fma2(a1, w.x, acc[1][0]);  acc[1][1] = fma2(a1, w.y, acc[1][1]);
        acc[2][0] = fma2(a2, w.x, acc[2][0]);  acc[2][1] = fma2(a2, w.y, acc[2][1]);
        acc[3][0] = fma2(a3, w.x, acc[3][0]);  acc[3][1] = fma2(a3, w.y, acc[3][1]);
    }
    __syncthreads();

    {
        const float4* gs = reinterpret_cast<const float4*>(g_sum);
        #pragma unroll
        for (int i = 0; i < 4; i++) {
            int idx = tid + 256 * i;
            int r = idx >> 4, c = idx & 15;
            int grow = row0 + r;
            float4 v = make_float4(0.f, 0.f, 0.f, 0.f);
            if (grow < n_rows) {
                v = gs[(size_t)grow * 16 + c];
                float inv = sinv[r];
                v.x *= inv; v.y *= inv; v.z *= inv; v.w *= inv;
            }
            float2* dstp = &sA2[r * SA2_STRIDE + c * 4];
            dstp[0] = make_float2(v.x, v.x);
            dstp[1] = make_float2(v.y, v.y);
            dstp[2] = make_float2(v.z, v.z);
            dstp[3] = make_float2(v.w, v.w);
        }
    }
    __syncthreads();

    #pragma unroll 16
    for (int k = 0; k < FEATS; k++) {
        ulonglong2 w = *reinterpret_cast<const ulonglong2*>(&sWn[k * 16 + tx]);
        unsigned long long a0 = a0p[k], a1 = a1p[k], a2 = a2p[k], a3 = a3p[k];
        acc[0][0] = fma2(a0, w.x, acc[0][0]);  acc[0][1] = fma2(a0, w.y, acc[0][1]);
        acc[1][0] = fma2(a1, w.x, acc[1][0]);  acc[1][1] = fma2(a1, w.y, acc[1][1]);
        acc[2][0] = fma2(a2, w.x, acc[2][0]);  acc[2][1] = fma2(a2, w.y, acc[2][1]);
        acc[3][0] = fma2(a3, w.x, acc[3][0]);  acc[3][1] = fma2(a3, w.y, acc[3][1]);
    }

    float4 bb = reinterpret_cast<const float4*>(sb)[tx];
    float4* out4 = reinterpret_cast<float4*>(out);
    #pragma unroll
    for (int r = 0; r < 4; r++) {
        int row = row0 + ty * 4 + r;
        if (row < n_rows) {
            float2 p01 = *reinterpret_cast<float2*>(&acc[r][0]);
            float2 p23 = *reinterpret_cast<float2*>(&acc[r][1]);
            float4 o;
            o.x = fmaxf(p01.x + bb.x, 0.f);
            o.y = fmaxf(p01.y + bb.y, 0.f);
            o.z = fmaxf(p23.x + bb.z, 0.f);
            o.w = fmaxf(p23.y + bb.w, 0.f);
            out4[(size_t)row * 16 + tx] = o;
        }
    }
}

// ---------------------------------------------------------------------------
// Launch
// ---------------------------------------------------------------------------
extern "C" void kernel_launch(void* const* d_in, const int* in_sizes, int n_in,
                              void* d_out, int out_size) {
    const float* x   = (const float*)d_in[0];
    const float* Ws  = (const float*)d_in[1];
    const float* Wn  = (const float*)d_in[2];
    const float* b   = (const float*)d_in[3];
    const int*   src = (const int*)d_in[4];
    const int*   dst = (const int*)d_in[5];
    float* out = (float*)d_out;

    int n_edges = in_sizes[4];
    if (n_edges > MAX_EDGES) n_edges = MAX_EDGES;
    int n_rows = out_size / FEATS;
    if (n_rows > MAX_NODES) n_rows = MAX_NODES;
    int n_x_rows = in_sizes[0] / FEATS;      // rows of x (gather may index any)
    if (n_x_rows > MAX_NODES) n_x_rows = MAX_NODES;

    int nb_nodes = (n_rows + 255) / 256;
    int nb_edges = (n_edges + 255) / 256;
    int nb_scan  = (n_rows + SCAN_BLK - 1) / SCAN_BLK;   // <= 128

    zero_counts<<<nb_nodes, 256>>>(n_rows);
    hist_kernel<<<nb_edges, 256>>>(dst, n_edges);
    {
        int n4 = n_x_rows * (FEATS / 4);
        tohalf_kernel<<<(n4 + 255) / 256, 256>>>(x, n4);
    }
    scan1<<<nb_scan, SCAN_BLK>>>(n_rows);
    scan3<<<nb_nodes, 256>>>(n_rows, nb_scan);
    reorder_kernel<<<nb_edges, 256>>>(src, dst, n_edges);

    {
        long long threads_total = (long long)n_rows * 16;
        int blocks = (int)((threads_total + 255) / 256);
        gather_kernel<<<blocks, 256>>>(n_rows);
    }

    {
        static int smem_set = 0;
        if (!smem_set) {
            cudaFuncSetAttribute(out_kernel,
                                 cudaFuncAttributeMaxDynamicSharedMemorySize,
                                 SMEM_TOTAL);
            smem_set = 1;
        }
        int blocks = (n_rows + 63) / 64;
        out_kernel<<<blocks, 256, SMEM_TOTAL>>>(x, Ws, Wn, b, out, n_rows);
    }
}

// round 10
// speedup vs baseline: 1.1751x; 1.1751x over previous
#include <cuda_runtime.h>
#include <cuda_bf16.h>

#define FEATS 64
#define MAX_NODES 100000
#define MAX_EDGES 1000000
#define SCAN_BLK 1024

// ---- scratch (__device__ globals; no allocs allowed) ----
__device__ float g_sum[(size_t)MAX_NODES * FEATS];
__device__ float g_deg[MAX_NODES];
__device__ int   g_count[MAX_NODES];
__device__ int   g_incl[MAX_NODES];
__device__ int   g_start[MAX_NODES];
__device__ int   g_cursor[MAX_NODES];
__device__ int   g_blocksums[128];
__device__ int   g_edge_src[MAX_EDGES];

// ---------------------------------------------------------------------------
// packed f32x2 helpers (sm_103a)
// ---------------------------------------------------------------------------
__device__ __forceinline__ unsigned long long fma2(unsigned long long a,
                                                   unsigned long long b,
                                                   unsigned long long c) {
    unsigned long long d;
    asm("fma.rn.f32x2 %0, %1, %2, %3;" : "=l"(d) : "l"(a), "l"(b), "l"(c));
    return d;
}
__device__ __forceinline__ unsigned long long pack2(float v) {
    unsigned long long d;
    asm("mov.b64 %0, {%1, %1};" : "=l"(d) : "f"(v));
    return d;
}

// ---------------------------------------------------------------------------
// 1) zero int degree counters
// ---------------------------------------------------------------------------
__global__ void zero_counts(int n_nodes) {
    int i = blockIdx.x * blockDim.x + threadIdx.x;
    if (i < n_nodes) g_count[i] = 0;
}

// ---------------------------------------------------------------------------
// 2) histogram of dst (scalar — proven fastest)
// ---------------------------------------------------------------------------
__global__ void hist_kernel(const int* __restrict__ dst, int n_edges) {
    int e = blockIdx.x * blockDim.x + threadIdx.x;
    if (e < n_edges) atomicAdd(&g_count[dst[e]], 1);
}

// ---------------------------------------------------------------------------
// 3a) coalesced per-block (1024) inclusive scan + block totals
// ---------------------------------------------------------------------------
__global__ __launch_bounds__(SCAN_BLK) void scan1(int n_nodes) {
    __shared__ int s[SCAN_BLK];
    int i = blockIdx.x * SCAN_BLK + threadIdx.x;
    int v = (i < n_nodes) ? g_count[i] : 0;
    s[threadIdx.x] = v;
    __syncthreads();
    #pragma unroll
    for (int off = 1; off < SCAN_BLK; off <<= 1) {
        int t = (threadIdx.x >= off) ? s[threadIdx.x - off] : 0;
        __syncthreads();
        s[threadIdx.x] += t;
        __syncthreads();
    }
    if (i < n_nodes) g_incl[i] = s[threadIdx.x];
    if (threadIdx.x == SCAN_BLK - 1) g_blocksums[blockIdx.x] = s[SCAN_BLK - 1];
}

// ---------------------------------------------------------------------------
// 3b) finalize: redundant scan of block sums + row starts + cursors + degree
// ---------------------------------------------------------------------------
__global__ __launch_bounds__(256) void scan3(int n_nodes, int nb) {
    __shared__ int sbs[128];
    int t = threadIdx.x;
    if (t < 128) sbs[t] = (t < nb) ? g_blocksums[t] : 0;
    __syncthreads();
    #pragma unroll
    for (int off = 1; off < 128; off <<= 1) {
        int v = 0;
        if (t < 128 && t >= off) v = sbs[t - off];
        __syncthreads();
        if (t < 128) sbs[t] += v;
        __syncthreads();
    }
    int i = blockIdx.x * 256 + t;
    if (i < n_nodes) {
        int chunk = i / SCAN_BLK;
        int pre = (chunk == 0) ? 0 : sbs[chunk - 1];
        int cnt = g_count[i];
        int st = g_incl[i] - cnt + pre;
        g_start[i]  = st;
        g_cursor[i] = st;
        g_deg[i]    = (float)cnt;
    }
}

// ---------------------------------------------------------------------------
// 4) reorder (scalar — proven fastest)
// ---------------------------------------------------------------------------
__global__ void reorder_kernel(const int* __restrict__ src,
                               const int* __restrict__ dst, int n_edges) {
    int e = blockIdx.x * blockDim.x + threadIdx.x;
    if (e < n_edges) {
        int p = atomicAdd(&g_cursor[dst[e]], 1);
        g_edge_src[p] = src[e];
    }
}

// ---------------------------------------------------------------------------
// 5) gather (round-6 version: fp32 float4, 16-lane group, no prefetch)
// ---------------------------------------------------------------------------
__global__ __launch_bounds__(256) void gather_kernel(const float* __restrict__ x,
                                                     int n_nodes) {
    int grp  = (blockIdx.x * blockDim.x + threadIdx.x) >> 4;
    int lane = threadIdx.x & 15;
    if (grp >= n_nodes) return;
    int s0  = g_start[grp];
    int deg = g_count[grp];
    const float4* x4 = reinterpret_cast<const float4*>(x);
    float4 acc = make_float4(0.f, 0.f, 0.f, 0.f);

    int j = 0;
    for (; j + 4 <= deg; j += 4) {
        int i0 = __ldg(&g_edge_src[s0 + j + 0]);
        int i1 = __ldg(&g_edge_src[s0 + j + 1]);
        int i2 = __ldg(&g_edge_src[s0 + j + 2]);
        int i3 = __ldg(&g_edge_src[s0 + j + 3]);
        float4 v0 = __ldg(&x4[(size_t)i0 * 16 + lane]);
        float4 v1 = __ldg(&x4[(size_t)i1 * 16 + lane]);
        float4 v2 = __ldg(&x4[(size_t)i2 * 16 + lane]);
        float4 v3 = __ldg(&x4[(size_t)i3 * 16 + lane]);
        acc.x += v0.x + v1.x + v2.x + v3.x;
        acc.y += v0.y + v1.y + v2.y + v3.y;
        acc.z += v0.z + v1.z + v2.z + v3.z;
        acc.w += v0.w + v1.w + v2.w + v3.w;
    }
    for (; j < deg; j++) {
        int i0 = __ldg(&g_edge_src[s0 + j]);
        float4 v = __ldg(&x4[(size_t)i0 * 16 + lane]);
        acc.x += v.x;  acc.y += v.y;  acc.z += v.z;  acc.w += v.w;
    }
    reinterpret_cast<float4*>(g_sum)[(size_t)grp * 16 + lane] = acc;
}

// ---------------------------------------------------------------------------
// 6) out = relu(x@Ws + (sum/max(deg,1))@Wn + b)
//    M-tile 128; 256 thr = ty(16: 8 rows) x tx(16: 4 cols).
//    A staged TRANSPOSED sAT[k][row] -> one LDS.128 = 4 packed row-pairs.
//    W duplicated into f32x2 lanes via mov.b64 (register side).
//    smem: sAT 64*132*4 = 33792 + sWs/sWn 16384*2 + sb 256 + sinv 512 = 67328
// ---------------------------------------------------------------------------
#define SAT_STRIDE 132
#define SAT_BYTES  (64 * SAT_STRIDE * 4)                  // 33792
#define OUT_SMEM   (SAT_BYTES + 2 * 16384 + 256 + 512)    // 67328

__global__ __launch_bounds__(256) void out_kernel(const float* __restrict__ x,
                                                  const float* __restrict__ Ws,
                                                  const float* __restrict__ Wn,
                                                  const float* __restrict__ b,
                                                  float* __restrict__ out,
                                                  int n_rows) {
    extern __shared__ char smem[];
    float*  sAT = reinterpret_cast<float*>(smem);                       // [64][132]
    float4* sWs = reinterpret_cast<float4*>(smem + SAT_BYTES);          // [64][16]
    float4* sWn = reinterpret_cast<float4*>(smem + SAT_BYTES + 16384);
    float*  sb   = reinterpret_cast<float*>(smem + SAT_BYTES + 32768);  // [64]
    float*  sinv = sb + 64;                                             // [128]

    int tid  = threadIdx.x;
    int row0 = blockIdx.x * 128;

    // Stage weights + bias + inverse degrees
    {
        const float4* gWs = reinterpret_cast<const float4*>(Ws);
        const float4* gWn = reinterpret_cast<const float4*>(Wn);
        #pragma unroll
        for (int i = 0; i < 4; i++) {
            int idx = tid + 256 * i;
            sWs[idx] = __ldg(&gWs[idx]);
            sWn[idx] = __ldg(&gWn[idx]);
        }
        if (tid < FEATS) sb[tid] = b[tid];
        if (tid < 128) {
            int r = row0 + tid;
            float dg = (r < n_rows) ? g_deg[r] : 1.0f;
            sinv[tid] = 1.0f / fmaxf(dg, 1.0f);
        }
    }

    // Stage phase-1 A (x), transposed: sAT[k][r] = x[row0+r][k]
    {
        const float4* gx = reinterpret_cast<const float4*>(x);
        #pragma unroll
        for (int i = 0; i < 8; i++) {
            int idx = tid + 256 * i;       // 0..2047
            int r = idx >> 4;              // 0..127
            int c = idx & 15;              // k-group
            int grow = row0 + r;
            float4 v = make_float4(0.f, 0.f, 0.f, 0.f);
            if (grow < n_rows) v = __ldg(&gx[(size_t)grow * 16 + c]);
            sAT[(4 * c + 0) * SAT_STRIDE + r] = v.x;
            sAT[(4 * c + 1) * SAT_STRIDE + r] = v.y;
            sAT[(4 * c + 2) * SAT_STRIDE + r] = v.z;
            sAT[(4 * c + 3) * SAT_STRIDE + r] = v.w;
        }
    }
    __syncthreads();

    int ty = tid >> 4;               // 0..15 -> rows ty*8 .. ty*8+7
    int tx = tid & 15;               // 0..15 -> cols tx*4 .. tx*4+3
    int rbase = ty * 8;

    unsigned long long acc[4][4];    // [row-pair][col]
    #pragma unroll
    for (int p = 0; p < 4; p++)
        #pragma unroll
        for (int c = 0; c < 4; c++) acc[p][c] = 0ull;

    // Phase 1: x @ Ws
    #pragma unroll 8
    for (int k = 0; k < FEATS; k++) {
        const float* ap = &sAT[k * SAT_STRIDE + rbase];
        ulonglong2 A01 = *reinterpret_cast<const ulonglong2*>(ap);       // rows 0-3
        ulonglong2 A23 = *reinterpret_cast<const ulonglong2*>(ap + 4);   // rows 4-7
        float4 w = sWs[k * 16 + tx];
        unsigned long long w0 = pack2(w.x), w1 = pack2(w.y),
                           w2 = pack2(w.z), w3 = pack2(w.w);
        acc[0][0]=fma2(A01.x,w0,acc[0][0]); acc[0][1]=fma2(A01.x,w1,acc[0][1]);
        acc[0][2]=fma2(A01.x,w2,acc[0][2]); acc[0][3]=fma2(A01.x,w3,acc[0][3]);
        acc[1][0]=fma2(A01.y,w0,acc[1][0]); acc[1][1]=fma2(A01.y,w1,acc[1][1]);
        acc[1][2]=fma2(A01.y,w2,acc[1][2]); acc[1][3]=fma2(A01.y,w3,acc[1][3]);
        acc[2][0]=fma2(A23.x,w0,acc[2][0]); acc[2][1]=fma2(A23.x,w1,acc[2][1]);
        acc[2][2]=fma2(A23.x,w2,acc[2][2]); acc[2][3]=fma2(A23.x,w3,acc[2][3]);
        acc[3][0]=fma2(A23.y,w0,acc[3][0]); acc[3][1]=fma2(A23.y,w1,acc[3][1]);
        acc[3][2]=fma2(A23.y,w2,acc[3][2]); acc[3][3]=fma2(A23.y,w3,acc[3][3]);
    }
    __syncthreads();

    // Restage A with mean-scaled neighbor sums (transposed)
    {
        const float4* gs = reinterpret_cast<const float4*>(g_sum);
        #pragma unroll
        for (int i = 0; i < 8; i++) {
            int idx = tid + 256 * i;
            int r = idx >> 4;
            int c = idx & 15;
            int grow = row0 + r;
            float4 v = make_float4(0.f, 0.f, 0.f, 0.f);
            if (grow < n_rows) {
                v = gs[(size_t)grow * 16 + c];
                float inv = sinv[r];
                v.x *= inv; v.y *= inv; v.z *= inv; v.w *= inv;
            }
            sAT[(4 * c + 0) * SAT_STRIDE + r] = v.x;
            sAT[(4 * c + 1) * SAT_STRIDE + r] = v.y;
            sAT[(4 * c + 2) * SAT_STRIDE + r] = v.z;
            sAT[(4 * c + 3) * SAT_STRIDE + r] = v.w;
        }
    }
    __syncthreads();

    // Phase 2: h_neigh @ Wn (accumulate)
    #pragma unroll 8
    for (int k = 0; k < FEATS; k++) {
        const float* ap = &sAT[k * SAT_STRIDE + rbase];
        ulonglong2 A01 = *reinterpret_cast<const ulonglong2*>(ap);
        ulonglong2 A23 = *reinterpret_cast<const ulonglong2*>(ap + 4);
        float4 w = sWn[k * 16 + tx];
        unsigned long long w0 = pack2(w.x), w1 = pack2(w.y),
                           w2 = pack2(w.z), w3 = pack2(w.w);
        acc[0][0]=fma2(A01.x,w0,acc[0][0]); acc[0][1]=fma2(A01.x,w1,acc[0][1]);
        acc[0][2]=fma2(A01.x,w2,acc[0][2]); acc[0][3]=fma2(A01.x,w3,acc[0][3]);
        acc[1][0]=fma2(A01.y,w0,acc[1][0]); acc[1][1]=fma2(A01.y,w1,acc[1][1]);
        acc[1][2]=fma2(A01.y,w2,acc[1][2]); acc[1][3]=fma2(A01.y,w3,acc[1][3]);
        acc[2][0]=fma2(A23.x,w0,acc[2][0]); acc[2][1]=fma2(A23.x,w1,acc[2][1]);
        acc[2][2]=fma2(A23.x,w2,acc[2][2]); acc[2][3]=fma2(A23.x,w3,acc[2][3]);
        acc[3][0]=fma2(A23.y,w0,acc[3][0]); acc[3][1]=fma2(A23.y,w1,acc[3][1]);
        acc[3][2]=fma2(A23.y,w2,acc[3][2]); acc[3][3]=fma2(A23.y,w3,acc[3][3]);
    }

    // Epilogue: + b, relu, store (8 rows per thread)
    float4 bb = reinterpret_cast<const float4*>(sb)[tx];
    float4* out4 = reinterpret_cast<float4*>(out);
    #pragma unroll
    for (int p = 0; p < 4; p++) {
        float2 c0 = *reinterpret_cast<float2*>(&acc[p][0]);
        float2 c1 = *reinterpret_cast<float2*>(&acc[p][1]);
        float2 c2 = *reinterpret_cast<float2*>(&acc[p][2]);
        float2 c3 = *reinterpret_cast<float2*>(&acc[p][3]);
        int row_lo = row0 + rbase + 2 * p;
        if (row_lo < n_rows) {
            float4 o;
            o.x = fmaxf(c0.x + bb.x, 0.f);
            o.y = fmaxf(c1.x + bb.y, 0.f);
            o.z = fmaxf(c2.x + bb.z, 0.f);
            o.w = fmaxf(c3.x + bb.w, 0.f);
            out4[(size_t)row_lo * 16 + tx] = o;
        }
        int row_hi = row_lo + 1;
        if (row_hi < n_rows) {
            float4 o;
            o.x = fmaxf(c0.y + bb.x, 0.f);
            o.y = fmaxf(c1.y + bb.y, 0.f);
            o.z = fmaxf(c2.y + bb.z, 0.f);
            o.w = fmaxf(c3.y + bb.w, 0.f);
            out4[(size_t)row_hi * 16 + tx] = o;
        }
    }
}

// ---------------------------------------------------------------------------
// Launch
// ---------------------------------------------------------------------------
extern "C" void kernel_launch(void* const* d_in, const int* in_sizes, int n_in,
                              void* d_out, int out_size) {
    const float* x   = (const float*)d_in[0];
    const float* Ws  = (const float*)d_in[1];
    const float* Wn  = (const float*)d_in[2];
    const float* b   = (const float*)d_in[3];
    const int*   src = (const int*)d_in[4];
    const int*   dst = (const int*)d_in[5];
    float* out = (float*)d_out;

    int n_edges = in_sizes[4];
    if (n_edges > MAX_EDGES) n_edges = MAX_EDGES;
    int n_rows = out_size / FEATS;
    if (n_rows > MAX_NODES) n_rows = MAX_NODES;

    int nb_nodes = (n_rows + 255) / 256;
    int nb_edges = (n_edges + 255) / 256;
    int nb_scan  = (n_rows + SCAN_BLK - 1) / SCAN_BLK;

    zero_counts<<<nb_nodes, 256>>>(n_rows);
    hist_kernel<<<nb_edges, 256>>>(dst, n_edges);
    scan1<<<nb_scan, SCAN_BLK>>>(n_rows);
    scan3<<<nb_nodes, 256>>>(n_rows, nb_scan);
    reorder_kernel<<<nb_edges, 256>>>(src, dst, n_edges);

    {
        long long threads_total = (long long)n_rows * 16;
        int blocks = (int)((threads_total + 255) / 256);
        gather_kernel<<<blocks, 256>>>(x, n_rows);
    }

    {
        static int smem_set = 0;
        if (!smem_set) {
            cudaFuncSetAttribute(out_kernel,
                                 cudaFuncAttributeMaxDynamicSharedMemorySize,
                                 OUT_SMEM);
            smem_set = 1;
        }
        int blocks = (n_rows + 127) / 128;
        out_kernel<<<blocks, 256, OUT_SMEM>>>(x, Ws, Wn, b, out, n_rows);
    }
}

// round 12
// speedup vs baseline: 1.1959x; 1.0177x over previous
#include <cuda_runtime.h>
#include <cuda_bf16.h>

#define FEATS 64
#define MAX_NODES 100000
#define MAX_EDGES 1000000
#define SCAN_BLK 1024

// ---- scratch (__device__ globals; no allocs allowed) ----
__device__ float g_sum[(size_t)MAX_NODES * FEATS];
__device__ float g_deg[MAX_NODES];
__device__ int   g_count[MAX_NODES];
__device__ int   g_incl[MAX_NODES];
__device__ int   g_start[MAX_NODES];
__device__ int   g_cursor[MAX_NODES];
__device__ int   g_blocksums[128];
__device__ int   g_edge_src[MAX_EDGES];

// ---------------------------------------------------------------------------
// packed f32x2 helpers (sm_103a)
// ---------------------------------------------------------------------------
__device__ __forceinline__ unsigned long long fma2(unsigned long long a,
                                                   unsigned long long b,
                                                   unsigned long long c) {
    unsigned long long d;
    asm("fma.rn.f32x2 %0, %1, %2, %3;" : "=l"(d) : "l"(a), "l"(b), "l"(c));
    return d;
}
__device__ __forceinline__ unsigned long long pack2(float v) {
    unsigned long long d;
    asm("mov.b64 %0, {%1, %1};" : "=l"(d) : "f"(v));
    return d;
}

// ---------------------------------------------------------------------------
// 1) zero int degree counters
// ---------------------------------------------------------------------------
__global__ void zero_counts(int n_nodes) {
    int i = blockIdx.x * blockDim.x + threadIdx.x;
    if (i < n_nodes) g_count[i] = 0;
}

// ---------------------------------------------------------------------------
// 2) histogram of dst (scalar — proven fastest)
// ---------------------------------------------------------------------------
__global__ void hist_kernel(const int* __restrict__ dst, int n_edges) {
    int e = blockIdx.x * blockDim.x + threadIdx.x;
    if (e < n_edges) atomicAdd(&g_count[dst[e]], 1);
}

// ---------------------------------------------------------------------------
// 3a) per-block (1024) inclusive scan via warp shuffles (2 barriers)
// ---------------------------------------------------------------------------
__global__ __launch_bounds__(SCAN_BLK) void scan1(int n_nodes) {
    __shared__ int wsum[32];
    int tid  = threadIdx.x;
    int lane = tid & 31, wid = tid >> 5;
    int i = blockIdx.x * SCAN_BLK + tid;
    int v = (i < n_nodes) ? g_count[i] : 0;
    int s = v;
    #pragma unroll
    for (int off = 1; off < 32; off <<= 1) {
        int t = __shfl_up_sync(0xffffffffu, s, off);
        if (lane >= off) s += t;
    }
    if (lane == 31) wsum[wid] = s;
    __syncthreads();
    if (wid == 0) {
        int w = wsum[lane];
        #pragma unroll
        for (int off = 1; off < 32; off <<= 1) {
            int t = __shfl_up_sync(0xffffffffu, w, off);
            if (lane >= off) w += t;
        }
        wsum[lane] = w;
    }
    __syncthreads();
    int incl = s + (wid > 0 ? wsum[wid - 1] : 0);
    if (i < n_nodes) g_incl[i] = incl;
    if (tid == SCAN_BLK - 1) g_blocksums[blockIdx.x] = incl;
}

// ---------------------------------------------------------------------------
// 3b) finalize: redundant scan of block sums + row starts + cursors + degree
// ---------------------------------------------------------------------------
__global__ __launch_bounds__(256) void scan3(int n_nodes, int nb) {
    __shared__ int sbs[128];
    int t = threadIdx.x;
    if (t < 128) sbs[t] = (t < nb) ? g_blocksums[t] : 0;
    __syncthreads();
    #pragma unroll
    for (int off = 1; off < 128; off <<= 1) {
        int v = 0;
        if (t < 128 && t >= off) v = sbs[t - off];
        __syncthreads();
        if (t < 128) sbs[t] += v;
        __syncthreads();
    }
    int i = blockIdx.x * 256 + t;
    if (i < n_nodes) {
        int chunk = i / SCAN_BLK;
        int pre = (chunk == 0) ? 0 : sbs[chunk - 1];
        int cnt = g_count[i];
        int st = g_incl[i] - cnt + pre;
        g_start[i]  = st;
        g_cursor[i] = st;
        g_deg[i]    = (float)cnt;
    }
}

// ---------------------------------------------------------------------------
// 4) reorder (scalar — proven fastest)
// ---------------------------------------------------------------------------
__global__ void reorder_kernel(const int* __restrict__ src,
                               const int* __restrict__ dst, int n_edges) {
    int e = blockIdx.x * blockDim.x + threadIdx.x;
    if (e < n_edges) {
        int p = atomicAdd(&g_cursor[dst[e]], 1);
        g_edge_src[p] = src[e];
    }
}

// ---------------------------------------------------------------------------
// 5) gather (proven round-6/10 version: fp32 float4, 16-lane group)
// ---------------------------------------------------------------------------
__global__ __launch_bounds__(256) void gather_kernel(const float* __restrict__ x,
                                                     int n_nodes) {
    int grp  = (blockIdx.x * blockDim.x + threadIdx.x) >> 4;
    int lane = threadIdx.x & 15;
    if (grp >= n_nodes) return;
    int s0  = g_start[grp];
    int deg = g_count[grp];
    const float4* x4 = reinterpret_cast<const float4*>(x);
    float4 acc = make_float4(0.f, 0.f, 0.f, 0.f);

    int j = 0;
    for (; j + 4 <= deg; j += 4) {
        int i0 = __ldg(&g_edge_src[s0 + j + 0]);
        int i1 = __ldg(&g_edge_src[s0 + j + 1]);
        int i2 = __ldg(&g_edge_src[s0 + j + 2]);
        int i3 = __ldg(&g_edge_src[s0 + j + 3]);
        float4 v0 = __ldg(&x4[(size_t)i0 * 16 + lane]);
        float4 v1 = __ldg(&x4[(size_t)i1 * 16 + lane]);
        float4 v2 = __ldg(&x4[(size_t)i2 * 16 + lane]);
        float4 v3 = __ldg(&x4[(size_t)i3 * 16 + lane]);
        acc.x += v0.x + v1.x + v2.x + v3.x;
        acc.y += v0.y + v1.y + v2.y + v3.y;
        acc.z += v0.z + v1.z + v2.z + v3.z;
        acc.w += v0.w + v1.w + v2.w + v3.w;
    }
    for (; j < deg; j++) {
        int i0 = __ldg(&g_edge_src[s0 + j]);
        float4 v = __ldg(&x4[(size_t)i0 * 16 + lane]);
        acc.x += v.x;  acc.y += v.y;  acc.z += v.z;  acc.w += v.w;
    }
    reinterpret_cast<float4*>(g_sum)[(size_t)grp * 16 + lane] = acc;
}

// ---------------------------------------------------------------------------
// 6) out = relu(x@Ws + (sum/max(deg,1))@Wn + b)
//    Round-10 transposed-A FFMA2 GEMM, with remapped staging:
//    warp = 8 rows x 4 c-groups -> STS 2-way conflicts (was 8-way).
// ---------------------------------------------------------------------------
#define SAT_STRIDE 132
#define SAT_BYTES  (64 * SAT_STRIDE * 4)                  // 33792
#define OUT_SMEM   (SAT_BYTES + 2 * 16384 + 256 + 512)    // 67328

__global__ __launch_bounds__(256) void out_kernel(const float* __restrict__ x,
                                                  const float* __restrict__ Ws,
                                                  const float* __restrict__ Wn,
                                                  const float* __restrict__ b,
                                                  float* __restrict__ out,
                                                  int n_rows) {
    extern __shared__ char smem[];
    float*  sAT = reinterpret_cast<float*>(smem);                       // [64][132]
    float4* sWs = reinterpret_cast<float4*>(smem + SAT_BYTES);          // [64][16]
    float4* sWn = reinterpret_cast<float4*>(smem + SAT_BYTES + 16384);
    float*  sb   = reinterpret_cast<float*>(smem + SAT_BYTES + 32768);  // [64]
    float*  sinv = sb + 64;                                             // [128]

    int tid  = threadIdx.x;
    int row0 = blockIdx.x * 128;

    // Stage weights + bias + inverse degrees
    {
        const float4* gWs = reinterpret_cast<const float4*>(Ws);
        const float4* gWn = reinterpret_cast<const float4*>(Wn);
        #pragma unroll
        for (int i = 0; i < 4; i++) {
            int idx = tid + 256 * i;
            sWs[idx] = __ldg(&gWs[idx]);
            sWn[idx] = __ldg(&gWn[idx]);
        }
        if (tid < FEATS) sb[tid] = b[tid];
        if (tid < 128) {
            int r = row0 + tid;
            float dg = (r < n_rows) ? g_deg[r] : 1.0f;
            sinv[tid] = 1.0f / fmaxf(dg, 1.0f);
        }
    }

    // Stage phase-1 A (x), transposed, remapped: warp = 8 rows x 4 c-groups
    {
        const float4* gx = reinterpret_cast<const float4*>(x);
        #pragma unroll
        for (int i = 0; i < 8; i++) {
            int idx = tid + 256 * i;                 // 0..2047
            int r = (idx & 7) | ((idx >> 7) << 3);   // 0..127
            int c = ((idx >> 3) & 3) | (((idx >> 5) & 3) << 2);  // 0..15
            int grow = row0 + r;
            float4 v = make_float4(0.f, 0.f, 0.f, 0.f);
            if (grow < n_rows) v = __ldg(&gx[(size_t)grow * 16 + c]);
            sAT[(4 * c + 0) * SAT_STRIDE + r] = v.x;
            sAT[(4 * c + 1) * SAT_STRIDE + r] = v.y;
            sAT[(4 * c + 2) * SAT_STRIDE + r] = v.z;
            sAT[(4 * c + 3) * SAT_STRIDE + r] = v.w;
        }
    }
    __syncthreads();

    int ty = tid >> 4;               // 0..15 -> rows ty*8 .. ty*8+7
    int tx = tid & 15;               // 0..15 -> cols tx*4 .. tx*4+3
    int rbase = ty * 8;

    unsigned long long acc[4][4];    // [row-pair][col]
    #pragma unroll
    for (int p = 0; p < 4; p++)
        #pragma unroll
        for (int c = 0; c < 4; c++) acc[p][c] = 0ull;

    // Phase 1: x @ Ws
    #pragma unroll 8
    for (int k = 0; k < FEATS; k++) {
        const float* ap = &sAT[k * SAT_STRIDE + rbase];
        ulonglong2 A01 = *reinterpret_cast<const ulonglong2*>(ap);
        ulonglong2 A23 = *reinterpret_cast<const ulonglong2*>(ap + 4);
        float4 w = sWs[k * 16 + tx];
        unsigned long long w0 = pack2(w.x), w1 = pack2(w.y),
                           w2 = pack2(w.z), w3 = pack2(w.w);
        acc[0][0]=fma2(A01.x,w0,acc[0][0]); acc[0][1]=fma2(A01.x,w1,acc[0][1]);
        acc[0][2]=fma2(A01.x,w2,acc[0][2]); acc[0][3]=fma2(A01.x,w3,acc[0][3]);
        acc[1][0]=fma2(A01.y,w0,acc[1][0]); acc[1][1]=fma2(A01.y,w1,acc[1][1]);
        acc[1][2]=fma2(A01.y,w2,acc[1][2]); acc[1][3]=fma2(A01.y,w3,acc[1][3]);
        acc[2][0]=fma2(A23.x,w0,acc[2][0]); acc[2][1]=fma2(A23.x,w1,acc[2][1]);
        acc[2][2]=fma2(A23.x,w2,acc[2][2]); acc[2][3]=fma2(A23.x,w3,acc[2][3]);
        acc[3][0]=fma2(A23.y,w0,acc[3][0]); acc[3][1]=fma2(A23.y,w1,acc[3][1]);
        acc[3][2]=fma2(A23.y,w2,acc[3][2]); acc[3][3]=fma2(A23.y,w3,acc[3][3]);
    }
    __syncthreads();

    // Restage A with mean-scaled neighbor sums (transposed, remapped)
    {
        const float4* gs = reinterpret_cast<const float4*>(g_sum);
        #pragma unroll
        for (int i = 0; i < 8; i++) {
            int idx = tid + 256 * i;
            int r = (idx & 7) | ((idx >> 7) << 3);
            int c = ((idx >> 3) & 3) | (((idx >> 5) & 3) << 2);
            int grow = row0 + r;
            float4 v = make_float4(0.f, 0.f, 0.f, 0.f);
            if (grow < n_rows) {
                v = gs[(size_t)grow * 16 + c];
                float inv = sinv[r];
                v.x *= inv; v.y *= inv; v.z *= inv; v.w *= inv;
            }
            sAT[(4 * c + 0) * SAT_STRIDE + r] = v.x;
            sAT[(4 * c + 1) * SAT_STRIDE + r] = v.y;
            sAT[(4 * c + 2) * SAT_STRIDE + r] = v.z;
            sAT[(4 * c + 3) * SAT_STRIDE + r] = v.w;
        }
    }
    __syncthreads();

    // Phase 2: h_neigh @ Wn (accumulate)
    #pragma unroll 8
    for (int k = 0; k < FEATS; k++) {
        const float* ap = &sAT[k * SAT_STRIDE + rbase];
        ulonglong2 A01 = *reinterpret_cast<const ulonglong2*>(ap);
        ulonglong2 A23 = *reinterpret_cast<const ulonglong2*>(ap + 4);
        float4 w = sWn[k * 16 + tx];
        unsigned long long w0 = pack2(w.x), w1 = pack2(w.y),
                           w2 = pack2(w.z), w3 = pack2(w.w);
        acc[0][0]=fma2(A01.x,w0,acc[0][0]); acc[0][1]=fma2(A01.x,w1,acc[0][1]);
        acc[0][2]=fma2(A01.x,w2,acc[0][2]); acc[0][3]=fma2(A01.x,w3,acc[0][3]);
        acc[1][0]=fma2(A01.y,w0,acc[1][0]); acc[1][1]=fma2(A01.y,w1,acc[1][1]);
        acc[1][2]=fma2(A01.y,w2,acc[1][2]); acc[1][3]=fma2(A01.y,w3,acc[1][3]);
        acc[2][0]=fma2(A23.x,w0,acc[2][0]); acc[2][1]=fma2(A23.x,w1,acc[2][1]);
        acc[2][2]=fma2(A23.x,w2,acc[2][2]); acc[2][3]=fma2(A23.x,w3,acc[2][3]);
        acc[3][0]=fma2(A23.y,w0,acc[3][0]); acc[3][1]=fma2(A23.y,w1,acc[3][1]);
        acc[3][2]=fma2(A23.y,w2,acc[3][2]); acc[3][3]=fma2(A23.y,w3,acc[3][3]);
    }

    // Epilogue: + b, relu, store (8 rows per thread)
    float4 bb = reinterpret_cast<const float4*>(sb)[tx];
    float4* out4 = reinterpret_cast<float4*>(out);
    #pragma unroll
    for (int p = 0; p < 4; p++) {
        float2 c0 = *reinterpret_cast<float2*>(&acc[p][0]);
        float2 c1 = *reinterpret_cast<float2*>(&acc[p][1]);
        float2 c2 = *reinterpret_cast<float2*>(&acc[p][2]);
        float2 c3 = *reinterpret_cast<float2*>(&acc[p][3]);
        int row_lo = row0 + rbase + 2 * p;
        if (row_lo < n_rows) {
            float4 o;
            o.x = fmaxf(c0.x + bb.x, 0.f);
            o.y = fmaxf(c1.x + bb.y, 0.f);
            o.z = fmaxf(c2.x + bb.z, 0.f);
            o.w = fmaxf(c3.x + bb.w, 0.f);
            out4[(size_t)row_lo * 16 + tx] = o;
        }
        int row_hi = row_lo + 1;
        if (row_hi < n_rows) {
            float4 o;
            o.x = fmaxf(c0.y + bb.x, 0.f);
            o.y = fmaxf(c1.y + bb.y, 0.f);
            o.z = fmaxf(c2.y + bb.z, 0.f);
            o.w = fmaxf(c3.y + bb.w, 0.f);
            out4[(size_t)row_hi * 16 + tx] = o;
        }
    }
}

// ---------------------------------------------------------------------------
// Launch
// ---------------------------------------------------------------------------
extern "C" void kernel_launch(void* const* d_in, const int* in_sizes, int n_in,
                              void* d_out, int out_size) {
    const float* x   = (const float*)d_in[0];
    const float* Ws  = (const float*)d_in[1];
    const float* Wn  = (const float*)d_in[2];
    const float* b   = (const float*)d_in[3];
    const int*   src = (const int*)d_in[4];
    const int*   dst = (const int*)d_in[5];
    float* out = (float*)d_out;

    int n_edges = in_sizes[4];
    if (n_edges > MAX_EDGES) n_edges = MAX_EDGES;
    int n_rows = out_size / FEATS;
    if (n_rows > MAX_NODES) n_rows = MAX_NODES;

    int nb_nodes = (n_rows + 255) / 256;
    int nb_edges = (n_edges + 255) / 256;
    int nb_scan  = (n_rows + SCAN_BLK - 1) / SCAN_BLK;

    zero_counts<<<nb_nodes, 256>>>(n_rows);
    hist_kernel<<<nb_edges, 256>>>(dst, n_edges);
    scan1<<<nb_scan, SCAN_BLK>>>(n_rows);
    scan3<<<nb_nodes, 256>>>(n_rows, nb_scan);
    reorder_kernel<<<nb_edges, 256>>>(src, dst, n_edges);

    {
        long long threads_total = (long long)n_rows * 16;
        int blocks = (int)((threads_total + 255) / 256);
        gather_kernel<<<blocks, 256>>>(x, n_rows);
    }

    {
        static int smem_set = 0;
        if (!smem_set) {
            cudaFuncSetAttribute(out_kernel,
                                 cudaFuncAttributeMaxDynamicSharedMemorySize,
                                 OUT_SMEM);
            smem_set = 1;
        }
        int blocks = (n_rows + 127) / 128;
        out_kernel<<<blocks, 256, OUT_SMEM>>>(x, Ws, Wn, b, out, n_rows);
    }
}